// round 13
// baseline (speedup 1.0000x reference)
#include <cuda_runtime.h>
#include <cuda_fp16.h>
#include <cstdint>
#include <cstddef>

#define NU 150000
#define NB 75000
#define NE 1500000
#define DU 64
#define DB 128
#define HD 128

#define NBLK_U 147   // ceil(150000/1024)
#define NBLK_B 74    // ceil(75000/1024)
#define TB 586       // ceil(NB/128) tiles
#define TU 1172      // ceil(NU/128) tiles

// ---------------- scratch (fp16 hi-only activations) ---------------------------
__device__ __align__(16) __half g_uh0[(size_t)NU * HD];
__device__ __align__(16) __half g_uh1[(size_t)NU * HD];
__device__ __align__(16) __half g_bh0[(size_t)NB * HD];
__device__ __align__(16) __half g_bh1[(size_t)NB * HD];
__device__ __align__(16) __half g_mu0[(size_t)NU * HD];   // means, parity buffers
__device__ __align__(16) __half g_mu1[(size_t)NU * HD];
__device__ __align__(16) __half g_mb0[(size_t)NB * HD];
__device__ __align__(16) __half g_mb1[(size_t)NB * HD];
__device__ __align__(16) __half g_wlt[3 * 128 * 128];      // fp16 n-major Wl
__device__ __align__(16) __half g_wrt[3 * 128 * 128];      // fp16 n-major Wr
__device__ int g_deg_u[NU];
__device__ int g_deg_b[NB];
__device__ int g_offs_u[NU + 1];
__device__ int g_offs_b[NB + 1];
__device__ int g_bsum_u[NBLK_U + 1];
__device__ int g_bsum_b[NBLK_B + 1];
__device__ int g_cur_u[NU];
__device__ int g_cur_b[NB];
__device__ int g_csr_u[NE];
__device__ int g_csr_b[NE];

__device__ __forceinline__ __half* uh(int i) { return i ? g_uh1 : g_uh0; }
__device__ __forceinline__ __half* bh(int i) { return i ? g_bh1 : g_bh0; }
__device__ __forceinline__ __half* mu(int i) { return i ? g_mu1 : g_mu0; }
__device__ __forceinline__ __half* mb(int i) { return i ? g_mb1 : g_mb0; }

// ---------------- CSR build ---------------------------------------------------
__global__ void deg_kernel(const int* __restrict__ src, const int* __restrict__ dst) {
    int e = blockIdx.x * blockDim.x + threadIdx.x;
    if (e < NE) {
        atomicAdd(&g_deg_u[src[e]], 1);
        atomicAdd(&g_deg_b[dst[e]], 1);
    }
}

__global__ void __launch_bounds__(1024) scan_blocks(
        const int* __restrict__ deg, int* __restrict__ offs,
        int* __restrict__ bsum, int n) {
    __shared__ int wsum[32];
    const int tid = threadIdx.x;
    int i = blockIdx.x * 1024 + tid;
    int v = (i < n) ? deg[i] : 0;
    int x = v;
#pragma unroll
    for (int o = 1; o < 32; o <<= 1) {
        int y = __shfl_up_sync(0xffffffffu, x, o);
        if ((tid & 31) >= o) x += y;
    }
    if ((tid & 31) == 31) wsum[tid >> 5] = x;
    __syncthreads();
    if (tid < 32) {
        int w = wsum[tid];
#pragma unroll
        for (int o = 1; o < 32; o <<= 1) {
            int y = __shfl_up_sync(0xffffffffu, w, o);
            if (tid >= o) w += y;
        }
        wsum[tid] = w;
    }
    __syncthreads();
    int we = (tid >= 32) ? wsum[(tid >> 5) - 1] : 0;
    int incl = x + we;
    if (i < n) offs[i] = incl - v;
    if (tid == 1023) bsum[blockIdx.x] = incl;
}

__global__ void __launch_bounds__(256) scan_small(int* __restrict__ a, int L) {
    __shared__ int wsum[8];
    const int tid = threadIdx.x;
    int v = (tid < L) ? a[tid] : 0;
    int x = v;
#pragma unroll
    for (int o = 1; o < 32; o <<= 1) {
        int y = __shfl_up_sync(0xffffffffu, x, o);
        if ((tid & 31) >= o) x += y;
    }
    if ((tid & 31) == 31) wsum[tid >> 5] = x;
    __syncthreads();
    if (tid == 0) {
        int c = 0;
#pragma unroll
        for (int w = 0; w < 8; w++) { int t = wsum[w]; wsum[w] = c; c += t; }
    }
    __syncthreads();
    int excl = x - v + wsum[tid >> 5];
    if (tid < L) a[tid] = excl;
    if (tid == L) a[L] = excl;
}

__global__ void scan_add(int* __restrict__ offs, const int* __restrict__ bsum,
                         int* __restrict__ cur, int n, int nblk) {
    int i = blockIdx.x * blockDim.x + threadIdx.x;
    if (i < n) {
        int v = offs[i] + bsum[i >> 10];
        offs[i] = v;
        cur[i] = v;
    }
    if (i == 0) offs[n] = bsum[nblk];
}

__global__ void fill_kernel(const int* __restrict__ src, const int* __restrict__ dst) {
    int e = blockIdx.x * blockDim.x + threadIdx.x;
    if (e < NE) {
        int s = src[e], d = dst[e];
        g_csr_u[atomicAdd(&g_cur_u[s], 1)] = d;
        g_csr_b[atomicAdd(&g_cur_b[d], 1)] = s;
    }
}

// ---------------- weight pre-convert: fp32 k-major -> fp16 n-major -------------
__global__ void convert_w(const float* __restrict__ Wl, const float* __restrict__ Wr) {
    int i = blockIdx.x * blockDim.x + threadIdx.x;   // over 3*16384
    if (i < 3 * 16384) {
        int l = i >> 14, r = i & 16383;
        int n = r >> 7, k = r & 127;
        size_t srcoff = ((size_t)l << 14) + k * 128 + n;
        g_wlt[i] = __float2half_rn(Wl[srcoff]);
        g_wrt[i] = __float2half_rn(Wr[srcoff]);
    }
}

// ---------------- CSR gather (single direction, 1 warp / dst row) --------------
__global__ void __launch_bounds__(256) gather_mean(int is_user, int cur, int mbuf) {
    int w    = (blockIdx.x * blockDim.x + threadIdx.x) >> 5;
    int lane = threadIdx.x & 31;
    const int N = is_user ? NU : NB;
    if (w >= N) return;

    const __half* __restrict__ src = is_user ? bh(cur) : uh(cur);
    __half* __restrict__ out       = is_user ? mu(mbuf) : mb(mbuf);
    const int* __restrict__ offs   = is_user ? g_offs_u : g_offs_b;
    const int* __restrict__ idx    = is_user ? g_csr_u : g_csr_b;

    int s = offs[w], e = offs[w + 1];
    const int c4 = lane * 4;

    float ax = 0.f, ay = 0.f, az = 0.f, aw = 0.f;
    int j = s;
    for (; j + 4 <= e; j += 4) {
        int n0 = idx[j], n1 = idx[j + 1], n2 = idx[j + 2], n3 = idx[j + 3];
        uint2 r0 = *(const uint2*)(src + (size_t)n0 * HD + c4);
        uint2 r1 = *(const uint2*)(src + (size_t)n1 * HD + c4);
        uint2 r2 = *(const uint2*)(src + (size_t)n2 * HD + c4);
        uint2 r3 = *(const uint2*)(src + (size_t)n3 * HD + c4);
#pragma unroll
        for (int q = 0; q < 4; q++) {
            uint2 r = (q == 0) ? r0 : (q == 1) ? r1 : (q == 2) ? r2 : r3;
            float2 f0 = __half22float2(*(__half2*)&r.x);
            float2 f1 = __half22float2(*(__half2*)&r.y);
            ax += f0.x; ay += f0.y; az += f1.x; aw += f1.y;
        }
    }
    for (; j < e; j++) {
        uint2 r = *(const uint2*)(src + (size_t)idx[j] * HD + c4);
        float2 f0 = __half22float2(*(__half2*)&r.x);
        float2 f1 = __half22float2(*(__half2*)&r.y);
        ax += f0.x; ay += f0.y; az += f1.x; aw += f1.y;
    }
    float invd = 1.0f / fmaxf((float)(e - s), 1.0f);
    __half2 m01 = __float22half2_rn(make_float2(ax * invd, ay * invd));
    __half2 m23 = __float22half2_rn(make_float2(az * invd, aw * invd));
    uint2 o; o.x = *(uint32_t*)&m01; o.y = *(uint32_t*)&m23;
    *(uint2*)(out + (size_t)w * HD + c4) = o;
}

// ---------------- shared MMA helper --------------------------------------------
__device__ __forceinline__ void mma16816(float* d, const uint32_t* a,
                                         uint32_t b0, uint32_t b1) {
    asm volatile(
        "mma.sync.aligned.m16n8k16.row.col.f32.f16.f16.f32 "
        "{%0,%1,%2,%3}, {%4,%5,%6,%7}, {%8,%9}, {%0,%1,%2,%3};"
        : "+f"(d[0]), "+f"(d[1]), "+f"(d[2]), "+f"(d[3])
        : "r"(a[0]), "r"(a[1]), "r"(a[2]), "r"(a[3]), "r"(b0), "r"(b1));
}

#define AST 72    // fp16 k-stride in smem (conflict-free fragment loads)

// ---------------- projection GEMM via mma (merged user+book) -------------------
#define SMP_BIAS 0
#define SMP_AHI  1024
#define SMP_ALO  (SMP_AHI + 128 * AST * 2)
#define SMP_BHI  (SMP_ALO + 128 * AST * 2)
#define SMP_BLO  (SMP_BHI + 128 * AST * 2)
#define SMP_TOT  (SMP_BLO + 128 * AST * 2)

__global__ void __launch_bounds__(256, 2) proj_mma(
        const float* __restrict__ user_x, const float* __restrict__ book_x,
        const float* __restrict__ upw, const float* __restrict__ upb,
        const float* __restrict__ bpw, const float* __restrict__ bpb) {
    extern __shared__ char smem[];
    const int tid = threadIdx.x;
    const int wid = tid >> 5;
    const int lane = tid & 31;

    const float* A; const float* W; const float* bias;
    __half* Ch;
    int N, K, tile;
    if (blockIdx.x < TU) {
        A = user_x; W = upw; bias = upb; Ch = g_uh0;
        N = NU; K = DU; tile = blockIdx.x;
    } else {
        A = book_x; W = bpw; bias = bpb; Ch = g_bh0;
        N = NB; K = DB; tile = blockIdx.x - TU;
    }
    const int row0 = tile * 128;
    const int nchunks = K >> 6;

    if (tid < 128) *(float*)(smem + SMP_BIAS + tid * 4) = bias[tid];

    const int warp_r = wid >> 1;
    const int warp_c = wid & 1;
    const int gid = lane >> 2;
    const int tig = lane & 3;

    float acc[2][8][4];
#pragma unroll
    for (int t = 0; t < 2; t++)
#pragma unroll
        for (int j = 0; j < 8; j++)
#pragma unroll
            for (int q = 0; q < 4; q++) acc[t][j][q] = 0.f;

    const int a_kq = (tid & 15) * 4;
    const int a_m0 = tid >> 4;
    const int bn = tid & 127;
    const int bk0 = (tid >> 7) * 32;

#pragma unroll 1
    for (int c = 0; c < nchunks; c++) {
        __syncthreads();
        const int kc0 = c * 64;
#pragma unroll
        for (int i = 0; i < 8; i++) {
            int m = a_m0 + i * 16;
            int gr = row0 + m;
            float4 v = make_float4(0.f, 0.f, 0.f, 0.f);
            if (gr < N) v = *(const float4*)(A + (size_t)gr * K + kc0 + a_kq);
            __half2 h01 = __float22half2_rn(make_float2(v.x, v.y));
            __half2 h23 = __float22half2_rn(make_float2(v.z, v.w));
            float2 f01 = __half22float2(h01);
            float2 f23 = __half22float2(h23);
            __half2 l01 = __float22half2_rn(make_float2(v.x - f01.x, v.y - f01.y));
            __half2 l23 = __float22half2_rn(make_float2(v.z - f23.x, v.w - f23.y));
            uint32_t off = (uint32_t)(m * AST + a_kq) * 2;
            *(__half2*)(smem + SMP_AHI + off)     = h01;
            *(__half2*)(smem + SMP_AHI + off + 4) = h23;
            *(__half2*)(smem + SMP_ALO + off)     = l01;
            *(__half2*)(smem + SMP_ALO + off + 4) = l23;
        }
#pragma unroll 8
        for (int j = 0; j < 32; j++) {
            int kk = bk0 + j;
            float w = W[(size_t)(kc0 + kk) * 128 + bn];
            __half h = __float2half_rn(w);
            __half l = __float2half_rn(w - __half2float(h));
            uint32_t off = (uint32_t)(bn * AST + kk) * 2;
            *(__half*)(smem + SMP_BHI + off) = h;
            *(__half*)(smem + SMP_BLO + off) = l;
        }
        __syncthreads();

#pragma unroll
        for (int ks = 0; ks < 4; ks++) {
            const int k0 = ks * 16;
            uint32_t ahr[8], alr[8];
#pragma unroll
            for (int t = 0; t < 2; t++) {
                int r0 = warp_r * 32 + t * 16 + gid;
                uint32_t o0 = (uint32_t)(r0 * AST + k0 + tig * 2) * 2;
                uint32_t o1 = (uint32_t)((r0 + 8) * AST + k0 + tig * 2) * 2;
                ahr[t * 4 + 0] = *(const uint32_t*)(smem + SMP_AHI + o0);
                ahr[t * 4 + 1] = *(const uint32_t*)(smem + SMP_AHI + o1);
                ahr[t * 4 + 2] = *(const uint32_t*)(smem + SMP_AHI + o0 + 16);
                ahr[t * 4 + 3] = *(const uint32_t*)(smem + SMP_AHI + o1 + 16);
                alr[t * 4 + 0] = *(const uint32_t*)(smem + SMP_ALO + o0);
                alr[t * 4 + 1] = *(const uint32_t*)(smem + SMP_ALO + o1);
                alr[t * 4 + 2] = *(const uint32_t*)(smem + SMP_ALO + o0 + 16);
                alr[t * 4 + 3] = *(const uint32_t*)(smem + SMP_ALO + o1 + 16);
            }
#pragma unroll
            for (int j = 0; j < 8; j++) {
                int n = warp_c * 64 + j * 8 + gid;
                uint32_t ob = (uint32_t)(n * AST + k0 + tig * 2) * 2;
                uint32_t bh0 = *(const uint32_t*)(smem + SMP_BHI + ob);
                uint32_t bh1 = *(const uint32_t*)(smem + SMP_BHI + ob + 16);
                uint32_t bl0 = *(const uint32_t*)(smem + SMP_BLO + ob);
                uint32_t bl1 = *(const uint32_t*)(smem + SMP_BLO + ob + 16);
#pragma unroll
                for (int t = 0; t < 2; t++) {
                    mma16816(acc[t][j], ahr + t * 4, bh0, bh1);
                    mma16816(acc[t][j], ahr + t * 4, bl0, bl1);
                    mma16816(acc[t][j], alr + t * 4, bh0, bh1);
                }
            }
        }
    }

    const float* bias_s = (const float*)(smem + SMP_BIAS);
#pragma unroll
    for (int t = 0; t < 2; t++) {
        int r_lo = row0 + warp_r * 32 + t * 16 + gid;
        int r_hi = r_lo + 8;
#pragma unroll
        for (int j = 0; j < 8; j++) {
            int col = warp_c * 64 + j * 8 + tig * 2;
            float bx = bias_s[col], by = bias_s[col + 1];
            if (r_lo < N) {
                __half2 h = __float22half2_rn(
                    make_float2(acc[t][j][0] + bx, acc[t][j][1] + by));
                *(__half2*)(Ch + (size_t)r_lo * 128 + col) = h;
            }
            if (r_hi < N) {
                __half2 h = __float22half2_rn(
                    make_float2(acc[t][j][2] + bx, acc[t][j][3] + by));
                *(__half2*)(Ch + (size_t)r_hi * 128 + col) = h;
            }
        }
    }
}

// ---------------- tensor-core SAGE GEMM (single direction, SW-pipelined) -------
#define SMG_BIAS 0
#define SMG_A    1024
#define SMG_B    (SMG_A + 128 * AST * 2)
#define SMG_TOT  (SMG_B + 128 * AST * 2)

__global__ void __launch_bounds__(256, 2) sage_mma(
        int is_user, int cur, int mbuf,
        const __half* __restrict__ Wlt, const __half* __restrict__ Wrt,
        const float* __restrict__ bias) {
    extern __shared__ char smem[];
    const int tid = threadIdx.x;
    const int wid = tid >> 5;
    const int lane = tid & 31;

    const int tile = blockIdx.x;
    const __half* __restrict__ meanh = is_user ? mu(mbuf) : mb(mbuf);
    const __half* __restrict__ Xh    = is_user ? uh(cur) : bh(cur);
    __half* __restrict__ Oh          = is_user ? uh(cur ^ 1) : bh(cur ^ 1);
    const int N = is_user ? NU : NB;
    const int row0 = tile * 128;

    if (tid < 128) *(float*)(smem + SMG_BIAS + tid * 4) = bias[tid];

    const int warp_r = wid >> 1;
    const int warp_c = wid & 1;
    const int gid = lane >> 2;
    const int tig = lane & 3;

    float acc[2][8][4];
#pragma unroll
    for (int t = 0; t < 2; t++)
#pragma unroll
        for (int j = 0; j < 8; j++)
#pragma unroll
            for (int q = 0; q < 4; q++) acc[t][j][q] = 0.f;

    const int a_kq = (tid & 15) * 4;
    const int a_m0 = tid >> 4;
    const int bn = tid & 127;
    const int bk0 = (tid >> 7) * 32;

    // prefetch registers (chunk operands)
    uint2 aR[8];
    uint4 bR[4];

    // load chunk c operands into regs
#define LOADC(cc) do {                                                          \
        const int _kg0 = (cc) * 64;                                             \
        const bool _xp = (_kg0 >= 128);                                         \
        const __half* _as = _xp ? Xh : meanh;                                   \
        const int _ak = _xp ? _kg0 - 128 : _kg0;                                \
        _Pragma("unroll")                                                        \
        for (int i = 0; i < 8; i++) {                                           \
            int gr = row0 + a_m0 + i * 16;                                      \
            aR[i] = make_uint2(0u, 0u);                                         \
            if (gr < N) aR[i] = *(const uint2*)(_as + (size_t)gr * 128 + _ak + a_kq); \
        }                                                                        \
        const __half* _ws = (_xp ? Wrt : Wlt) + (size_t)bn * 128 + _ak + bk0;   \
        _Pragma("unroll")                                                        \
        for (int j = 0; j < 4; j++) bR[j] = *(const uint4*)(_ws + j * 8);       \
    } while (0)

    LOADC(0);

#pragma unroll 1
    for (int c = 0; c < 4; c++) {
        // drain regs -> smem
#pragma unroll
        for (int i = 0; i < 8; i++)
            *(uint2*)(smem + SMG_A + (uint32_t)((a_m0 + i * 16) * AST + a_kq) * 2) = aR[i];
#pragma unroll
        for (int j = 0; j < 4; j++)
            *(uint4*)(smem + SMG_B + (uint32_t)(bn * AST + bk0 + j * 8) * 2) = bR[j];
        __syncthreads();

        // issue next chunk's global loads (latency overlaps compute below)
        if (c < 3) LOADC(c + 1);

        // compute chunk c
#pragma unroll
        for (int ks = 0; ks < 4; ks++) {
            const int k0 = ks * 16;
            uint32_t ahr[8];
#pragma unroll
            for (int t = 0; t < 2; t++) {
                int r0 = warp_r * 32 + t * 16 + gid;
                uint32_t o0 = (uint32_t)(r0 * AST + k0 + tig * 2) * 2;
                uint32_t o1 = (uint32_t)((r0 + 8) * AST + k0 + tig * 2) * 2;
                ahr[t * 4 + 0] = *(const uint32_t*)(smem + SMG_A + o0);
                ahr[t * 4 + 1] = *(const uint32_t*)(smem + SMG_A + o1);
                ahr[t * 4 + 2] = *(const uint32_t*)(smem + SMG_A + o0 + 16);
                ahr[t * 4 + 3] = *(const uint32_t*)(smem + SMG_A + o1 + 16);
            }
#pragma unroll
            for (int j = 0; j < 8; j++) {
                int n = warp_c * 64 + j * 8 + gid;
                uint32_t ob = (uint32_t)(n * AST + k0 + tig * 2) * 2;
                uint32_t bh0 = *(const uint32_t*)(smem + SMG_B + ob);
                uint32_t bh1 = *(const uint32_t*)(smem + SMG_B + ob + 16);
#pragma unroll
                for (int t = 0; t < 2; t++)
                    mma16816(acc[t][j], ahr + t * 4, bh0, bh1);
            }
        }
        __syncthreads();
    }
#undef LOADC

    const float* bias_s = (const float*)(smem + SMG_BIAS);
#pragma unroll
    for (int t = 0; t < 2; t++) {
        int r_lo = row0 + warp_r * 32 + t * 16 + gid;
        int r_hi = r_lo + 8;
#pragma unroll
        for (int j = 0; j < 8; j++) {
            int col = warp_c * 64 + j * 8 + tig * 2;
            float bx = bias_s[col], by = bias_s[col + 1];
            if (r_lo < N) {
                __half2 h = __float22half2_rn(make_float2(
                    fmaxf(acc[t][j][0] + bx, 0.f), fmaxf(acc[t][j][1] + by, 0.f)));
                *(__half2*)(Oh + (size_t)r_lo * 128 + col) = h;
            }
            if (r_hi < N) {
                __half2 h = __float22half2_rn(make_float2(
                    fmaxf(acc[t][j][2] + bx, 0.f), fmaxf(acc[t][j][3] + by, 0.f)));
                *(__half2*)(Oh + (size_t)r_hi * 128 + col) = h;
            }
        }
    }
}

// ---------------- layernorm (both populations, 1 warp / row) -------------------
__global__ void __launch_bounds__(256) ln_kernel(
        int cur,
        const float* __restrict__ ug, const float* __restrict__ ube,
        const float* __restrict__ bg, const float* __restrict__ bbe,
        float* __restrict__ out) {
    int gw   = (blockIdx.x * blockDim.x + threadIdx.x) >> 5;
    int lane = threadIdx.x & 31;
    if (gw >= NU + NB) return;

    int is_user = (gw < NU);
    int w = is_user ? gw : gw - NU;
    const __half* __restrict__ Xh = is_user ? uh(cur) : bh(cur);
    const float* gamma = is_user ? ug : bg;
    const float* beta  = is_user ? ube : bbe;
    float* op = out + (size_t)gw * 128;

    uint2 vh = *(const uint2*)(Xh + (size_t)w * 128 + lane * 4);
    float2 h0 = __half22float2(*(__half2*)&vh.x);
    float2 h1 = __half22float2(*(__half2*)&vh.y);
    float4 v;
    v.x = h0.x; v.y = h0.y; v.z = h1.x; v.w = h1.y;

    float s = v.x + v.y + v.z + v.w;
#pragma unroll
    for (int o = 16; o; o >>= 1) s += __shfl_xor_sync(0xffffffffu, s, o);
    float mean = s * (1.0f / 128.0f);

    float dx = v.x - mean, dy = v.y - mean, dz = v.z - mean, dw = v.w - mean;
    float q = dx * dx + dy * dy + dz * dz + dw * dw;
#pragma unroll
    for (int o = 16; o; o >>= 1) q += __shfl_xor_sync(0xffffffffu, q, o);
    float rs = rsqrtf(q * (1.0f / 128.0f) + 1e-5f);

    float4 g  = *(const float4*)(gamma + lane * 4);
    float4 bt = *(const float4*)(beta + lane * 4);
    float4 o4;
    o4.x = dx * rs * g.x + bt.x;
    o4.y = dy * rs * g.y + bt.y;
    o4.z = dz * rs * g.z + bt.z;
    o4.w = dw * rs * g.w + bt.w;
    *(float4*)(op + lane * 4) = o4;
}

// ---------------- launch --------------------------------------------------------
extern "C" void kernel_launch(void* const* d_in, const int* in_sizes, int n_in,
                              void* d_out, int out_size) {
    const float* user_x = (const float*)d_in[0];
    const float* book_x = (const float*)d_in[1];
    const int*   esrc   = (const int*)d_in[2];
    const int*   edst   = (const int*)d_in[3];
    const float* upw    = (const float*)d_in[4];
    const float* upb    = (const float*)d_in[5];
    const float* bpw    = (const float*)d_in[6];
    const float* bpb    = (const float*)d_in[7];
    const float* Wl     = (const float*)d_in[8];
    const float* bl_    = (const float*)d_in[9];
    const float* Wr     = (const float*)d_in[10];
    const float* ug     = (const float*)d_in[11];
    const float* ube    = (const float*)d_in[12];
    const float* bg     = (const float*)d_in[13];
    const float* bbe    = (const float*)d_in[14];
    float* out = (float*)d_out;

    (void)in_sizes; (void)n_in; (void)out_size;

    static cudaStream_t sB = 0, sU = 0;
    static cudaEvent_t evIn = 0, evProj = 0, evBuild = 0;
    static cudaEvent_t evSb[3], evSu[3];
    if (!sB) {
        cudaStreamCreateWithFlags(&sB, cudaStreamNonBlocking);
        cudaStreamCreateWithFlags(&sU, cudaStreamNonBlocking);
        cudaEventCreateWithFlags(&evIn, cudaEventDisableTiming);
        cudaEventCreateWithFlags(&evProj, cudaEventDisableTiming);
        cudaEventCreateWithFlags(&evBuild, cudaEventDisableTiming);
        for (int i = 0; i < 3; i++) {
            cudaEventCreateWithFlags(&evSb[i], cudaEventDisableTiming);
            cudaEventCreateWithFlags(&evSu[i], cudaEventDisableTiming);
        }
    }

    cudaFuncSetAttribute(proj_mma, cudaFuncAttributeMaxDynamicSharedMemorySize, SMP_TOT);
    cudaFuncSetAttribute(sage_mma, cudaFuncAttributeMaxDynamicSharedMemorySize, SMG_TOT);

    int* d_offs_u; cudaGetSymbolAddress((void**)&d_offs_u, g_offs_u);
    int* d_offs_b; cudaGetSymbolAddress((void**)&d_offs_b, g_offs_b);
    int* d_deg_u;  cudaGetSymbolAddress((void**)&d_deg_u,  g_deg_u);
    int* d_deg_b;  cudaGetSymbolAddress((void**)&d_deg_b,  g_deg_b);
    int* d_bsum_u; cudaGetSymbolAddress((void**)&d_bsum_u, g_bsum_u);
    int* d_bsum_b; cudaGetSymbolAddress((void**)&d_bsum_b, g_bsum_b);
    int* d_cur_u;  cudaGetSymbolAddress((void**)&d_cur_u,  g_cur_u);
    int* d_cur_b;  cudaGetSymbolAddress((void**)&d_cur_b,  g_cur_b);
    __half* d_wlt; cudaGetSymbolAddress((void**)&d_wlt, g_wlt);
    __half* d_wrt; cudaGetSymbolAddress((void**)&d_wrt, g_wrt);

    // ---- fork: proj chain on sB, CSR build on default stream ----
    cudaEventRecord(evIn, 0);
    cudaStreamWaitEvent(sB, evIn, 0);
    convert_w<<<(3 * 16384 + 255) / 256, 256, 0, sB>>>(Wl, Wr);
    proj_mma<<<TU + TB, 256, SMP_TOT, sB>>>(user_x, book_x, upw, upb, bpw, bpb);
    cudaEventRecord(evProj, sB);

    cudaMemsetAsync(d_deg_u, 0, NU * sizeof(int), 0);
    cudaMemsetAsync(d_deg_b, 0, NB * sizeof(int), 0);
    deg_kernel<<<(NE + 255) / 256, 256>>>(esrc, edst);
    scan_blocks<<<NBLK_U, 1024>>>(d_deg_u, d_offs_u, d_bsum_u, NU);
    scan_blocks<<<NBLK_B, 1024>>>(d_deg_b, d_offs_b, d_bsum_b, NB);
    scan_small<<<1, 256>>>(d_bsum_u, NBLK_U);
    scan_small<<<1, 256>>>(d_bsum_b, NBLK_B);
    scan_add<<<(NU + 255) / 256, 256>>>(d_offs_u, d_bsum_u, d_cur_u, NU, NBLK_U);
    scan_add<<<(NB + 255) / 256, 256>>>(d_offs_b, d_bsum_b, d_cur_b, NB, NBLK_B);
    fill_kernel<<<(NE + 255) / 256, 256>>>(esrc, edst);
    cudaEventRecord(evBuild, 0);

    cudaStreamWaitEvent(sB, evBuild, 0);
    cudaStreamWaitEvent(sU, evBuild, 0);
    cudaStreamWaitEvent(sU, evProj, 0);

    // ---- pipelined direction chains: book chain on sB, user chain on sU ----
    const int GBB = (int)(((size_t)NB * 32 + 255) / 256);
    const int GBU = (int)(((size_t)NU * 32 + 255) / 256);
    int cur = 0;
    for (int l = 0; l < 3; l++) {
        const __half* wlt = d_wlt + (size_t)l * 16384;
        const __half* wrt = d_wrt + (size_t)l * 16384;
        const float* bb = bl_ + (size_t)l * 128;

        if (l > 0) cudaStreamWaitEvent(sB, evSu[l - 1], 0);
        gather_mean<<<GBB, 256, 0, sB>>>(0, cur, l & 1);
        sage_mma<<<TB, 256, SMG_TOT, sB>>>(0, cur, l & 1, wlt, wrt, bb);
        cudaEventRecord(evSb[l], sB);

        if (l > 0) cudaStreamWaitEvent(sU, evSb[l - 1], 0);
        gather_mean<<<GBU, 256, 0, sU>>>(1, cur, l & 1);
        sage_mma<<<TU, 256, SMG_TOT, sU>>>(1, cur, l & 1, wlt, wrt, bb);
        cudaEventRecord(evSu[l], sU);

        cur ^= 1;
    }

    // ---- join on default stream, then layernorm ----
    cudaStreamWaitEvent(0, evSb[2], 0);
    cudaStreamWaitEvent(0, evSu[2], 0);
    ln_kernel<<<(int)(((size_t)(NU + NB) * 32 + 255) / 256), 256>>>(
        cur, ug, ube, bg, bbe, out);
}

// round 14
// speedup vs baseline: 1.0265x; 1.0265x over previous
#include <cuda_runtime.h>
#include <cuda_fp16.h>
#include <cstdint>
#include <cstddef>

#define NU 150000
#define NB 75000
#define NE 1500000
#define DU 64
#define DB 128
#define HD 128

#define NBLK_U 147   // ceil(150000/1024)
#define NBLK_B 74    // ceil(75000/1024)
#define TB 586       // ceil(NB/128) tiles
#define TU 1172      // ceil(NU/128) tiles

// ---------------- scratch (fp16 hi-only activations) ---------------------------
__device__ __align__(16) __half g_uh0[(size_t)NU * HD];
__device__ __align__(16) __half g_uh1[(size_t)NU * HD];
__device__ __align__(16) __half g_bh0[(size_t)NB * HD];
__device__ __align__(16) __half g_bh1[(size_t)NB * HD];
__device__ __align__(16) __half g_mu0[(size_t)NU * HD];   // means, parity buffers
__device__ __align__(16) __half g_mu1[(size_t)NU * HD];
__device__ __align__(16) __half g_mb0[(size_t)NB * HD];
__device__ __align__(16) __half g_mb1[(size_t)NB * HD];
__device__ __align__(16) __half g_wlt[3 * 128 * 128];      // fp16 n-major Wl
__device__ __align__(16) __half g_wrt[3 * 128 * 128];      // fp16 n-major Wr
__device__ int g_deg_u[NU];
__device__ int g_deg_b[NB];
__device__ int g_offs_u[NU + 1];
__device__ int g_offs_b[NB + 1];
__device__ int g_bsum_u[NBLK_U + 1];
__device__ int g_bsum_b[NBLK_B + 1];
__device__ int g_cur_u[NU];
__device__ int g_cur_b[NB];
__device__ int g_csr_u[NE];
__device__ int g_csr_b[NE];

__device__ __forceinline__ __half* uh(int i) { return i ? g_uh1 : g_uh0; }
__device__ __forceinline__ __half* bh(int i) { return i ? g_bh1 : g_bh0; }
__device__ __forceinline__ __half* mu(int i) { return i ? g_mu1 : g_mu0; }
__device__ __forceinline__ __half* mb(int i) { return i ? g_mb1 : g_mb0; }

// ---------------- CSR build ---------------------------------------------------
__global__ void deg_kernel(const int* __restrict__ src, const int* __restrict__ dst) {
    int e = blockIdx.x * blockDim.x + threadIdx.x;
    if (e < NE) {
        atomicAdd(&g_deg_u[src[e]], 1);
        atomicAdd(&g_deg_b[dst[e]], 1);
    }
}

__global__ void __launch_bounds__(1024) scan_blocks(
        const int* __restrict__ deg, int* __restrict__ offs,
        int* __restrict__ bsum, int n) {
    __shared__ int wsum[32];
    const int tid = threadIdx.x;
    int i = blockIdx.x * 1024 + tid;
    int v = (i < n) ? deg[i] : 0;
    int x = v;
#pragma unroll
    for (int o = 1; o < 32; o <<= 1) {
        int y = __shfl_up_sync(0xffffffffu, x, o);
        if ((tid & 31) >= o) x += y;
    }
    if ((tid & 31) == 31) wsum[tid >> 5] = x;
    __syncthreads();
    if (tid < 32) {
        int w = wsum[tid];
#pragma unroll
        for (int o = 1; o < 32; o <<= 1) {
            int y = __shfl_up_sync(0xffffffffu, w, o);
            if (tid >= o) w += y;
        }
        wsum[tid] = w;
    }
    __syncthreads();
    int we = (tid >= 32) ? wsum[(tid >> 5) - 1] : 0;
    int incl = x + we;
    if (i < n) offs[i] = incl - v;
    if (tid == 1023) bsum[blockIdx.x] = incl;
}

__global__ void __launch_bounds__(256) scan_small(int* __restrict__ a, int L) {
    __shared__ int wsum[8];
    const int tid = threadIdx.x;
    int v = (tid < L) ? a[tid] : 0;
    int x = v;
#pragma unroll
    for (int o = 1; o < 32; o <<= 1) {
        int y = __shfl_up_sync(0xffffffffu, x, o);
        if ((tid & 31) >= o) x += y;
    }
    if ((tid & 31) == 31) wsum[tid >> 5] = x;
    __syncthreads();
    if (tid == 0) {
        int c = 0;
#pragma unroll
        for (int w = 0; w < 8; w++) { int t = wsum[w]; wsum[w] = c; c += t; }
    }
    __syncthreads();
    int excl = x - v + wsum[tid >> 5];
    if (tid < L) a[tid] = excl;
    if (tid == L) a[L] = excl;
}

__global__ void scan_add(int* __restrict__ offs, const int* __restrict__ bsum,
                         int* __restrict__ cur, int n, int nblk) {
    int i = blockIdx.x * blockDim.x + threadIdx.x;
    if (i < n) {
        int v = offs[i] + bsum[i >> 10];
        offs[i] = v;
        cur[i] = v;
    }
    if (i == 0) offs[n] = bsum[nblk];
}

__global__ void fill_kernel(const int* __restrict__ src, const int* __restrict__ dst) {
    int e = blockIdx.x * blockDim.x + threadIdx.x;
    if (e < NE) {
        int s = src[e], d = dst[e];
        g_csr_u[atomicAdd(&g_cur_u[s], 1)] = d;
        g_csr_b[atomicAdd(&g_cur_b[d], 1)] = s;
    }
}

// ---------------- weight pre-convert: fp32 k-major -> fp16 n-major -------------
__global__ void convert_w(const float* __restrict__ Wl, const float* __restrict__ Wr) {
    int i = blockIdx.x * blockDim.x + threadIdx.x;
    if (i < 3 * 16384) {
        int l = i >> 14, r = i & 16383;
        int n = r >> 7, k = r & 127;
        size_t srcoff = ((size_t)l << 14) + k * 128 + n;
        g_wlt[i] = __float2half_rn(Wl[srcoff]);
        g_wrt[i] = __float2half_rn(Wr[srcoff]);
    }
}

// ---------------- CSR gather (single direction, 1 warp / dst row) --------------
__global__ void __launch_bounds__(256) gather_mean(int is_user, int cur, int mbuf) {
    int w    = (blockIdx.x * blockDim.x + threadIdx.x) >> 5;
    int lane = threadIdx.x & 31;
    const int N = is_user ? NU : NB;
    if (w >= N) return;

    const __half* __restrict__ src = is_user ? bh(cur) : uh(cur);
    __half* __restrict__ out       = is_user ? mu(mbuf) : mb(mbuf);
    const int* __restrict__ offs   = is_user ? g_offs_u : g_offs_b;
    const int* __restrict__ idx    = is_user ? g_csr_u : g_csr_b;

    int s = offs[w], e = offs[w + 1];
    const int c4 = lane * 4;

    float ax = 0.f, ay = 0.f, az = 0.f, aw = 0.f;
    int j = s;
    for (; j + 4 <= e; j += 4) {
        int n0 = idx[j], n1 = idx[j + 1], n2 = idx[j + 2], n3 = idx[j + 3];
        uint2 r0 = *(const uint2*)(src + (size_t)n0 * HD + c4);
        uint2 r1 = *(const uint2*)(src + (size_t)n1 * HD + c4);
        uint2 r2 = *(const uint2*)(src + (size_t)n2 * HD + c4);
        uint2 r3 = *(const uint2*)(src + (size_t)n3 * HD + c4);
#pragma unroll
        for (int q = 0; q < 4; q++) {
            uint2 r = (q == 0) ? r0 : (q == 1) ? r1 : (q == 2) ? r2 : r3;
            float2 f0 = __half22float2(*(__half2*)&r.x);
            float2 f1 = __half22float2(*(__half2*)&r.y);
            ax += f0.x; ay += f0.y; az += f1.x; aw += f1.y;
        }
    }
    for (; j < e; j++) {
        uint2 r = *(const uint2*)(src + (size_t)idx[j] * HD + c4);
        float2 f0 = __half22float2(*(__half2*)&r.x);
        float2 f1 = __half22float2(*(__half2*)&r.y);
        ax += f0.x; ay += f0.y; az += f1.x; aw += f1.y;
    }
    float invd = 1.0f / fmaxf((float)(e - s), 1.0f);
    __half2 m01 = __float22half2_rn(make_float2(ax * invd, ay * invd));
    __half2 m23 = __float22half2_rn(make_float2(az * invd, aw * invd));
    uint2 o; o.x = *(uint32_t*)&m01; o.y = *(uint32_t*)&m23;
    *(uint2*)(out + (size_t)w * HD + c4) = o;
}

// ---------------- shared MMA helper --------------------------------------------
__device__ __forceinline__ void mma16816(float* d, const uint32_t* a,
                                         uint32_t b0, uint32_t b1) {
    asm volatile(
        "mma.sync.aligned.m16n8k16.row.col.f32.f16.f16.f32 "
        "{%0,%1,%2,%3}, {%4,%5,%6,%7}, {%8,%9}, {%0,%1,%2,%3};"
        : "+f"(d[0]), "+f"(d[1]), "+f"(d[2]), "+f"(d[3])
        : "r"(a[0]), "r"(a[1]), "r"(a[2]), "r"(a[3]), "r"(b0), "r"(b1));
}

#define AST 72    // fp16 k-stride in smem (conflict-free fragment loads)

// ---------------- projection GEMM via mma (merged user+book) -------------------
#define SMP_BIAS 0
#define SMP_AHI  1024
#define SMP_ALO  (SMP_AHI + 128 * AST * 2)
#define SMP_BHI  (SMP_ALO + 128 * AST * 2)
#define SMP_BLO  (SMP_BHI + 128 * AST * 2)
#define SMP_TOT  (SMP_BLO + 128 * AST * 2)

__global__ void __launch_bounds__(256, 2) proj_mma(
        const float* __restrict__ user_x, const float* __restrict__ book_x,
        const float* __restrict__ upw, const float* __restrict__ upb,
        const float* __restrict__ bpw, const float* __restrict__ bpb) {
    extern __shared__ char smem[];
    const int tid = threadIdx.x;
    const int wid = tid >> 5;
    const int lane = tid & 31;

    const float* A; const float* W; const float* bias;
    __half* Ch;
    int N, K, tile;
    if (blockIdx.x < TU) {
        A = user_x; W = upw; bias = upb; Ch = g_uh0;
        N = NU; K = DU; tile = blockIdx.x;
    } else {
        A = book_x; W = bpw; bias = bpb; Ch = g_bh0;
        N = NB; K = DB; tile = blockIdx.x - TU;
    }
    const int row0 = tile * 128;
    const int nchunks = K >> 6;

    if (tid < 128) *(float*)(smem + SMP_BIAS + tid * 4) = bias[tid];

    const int warp_r = wid >> 1;
    const int warp_c = wid & 1;
    const int gid = lane >> 2;
    const int tig = lane & 3;

    float acc[2][8][4];
#pragma unroll
    for (int t = 0; t < 2; t++)
#pragma unroll
        for (int j = 0; j < 8; j++)
#pragma unroll
            for (int q = 0; q < 4; q++) acc[t][j][q] = 0.f;

    const int a_kq = (tid & 15) * 4;
    const int a_m0 = tid >> 4;
    const int bn = tid & 127;
    const int bk0 = (tid >> 7) * 32;

#pragma unroll 1
    for (int c = 0; c < nchunks; c++) {
        __syncthreads();
        const int kc0 = c * 64;
#pragma unroll
        for (int i = 0; i < 8; i++) {
            int m = a_m0 + i * 16;
            int gr = row0 + m;
            float4 v = make_float4(0.f, 0.f, 0.f, 0.f);
            if (gr < N) v = *(const float4*)(A + (size_t)gr * K + kc0 + a_kq);
            __half2 h01 = __float22half2_rn(make_float2(v.x, v.y));
            __half2 h23 = __float22half2_rn(make_float2(v.z, v.w));
            float2 f01 = __half22float2(h01);
            float2 f23 = __half22float2(h23);
            __half2 l01 = __float22half2_rn(make_float2(v.x - f01.x, v.y - f01.y));
            __half2 l23 = __float22half2_rn(make_float2(v.z - f23.x, v.w - f23.y));
            uint32_t off = (uint32_t)(m * AST + a_kq) * 2;
            *(__half2*)(smem + SMP_AHI + off)     = h01;
            *(__half2*)(smem + SMP_AHI + off + 4) = h23;
            *(__half2*)(smem + SMP_ALO + off)     = l01;
            *(__half2*)(smem + SMP_ALO + off + 4) = l23;
        }
#pragma unroll 8
        for (int j = 0; j < 32; j++) {
            int kk = bk0 + j;
            float w = W[(size_t)(kc0 + kk) * 128 + bn];
            __half h = __float2half_rn(w);
            __half l = __float2half_rn(w - __half2float(h));
            uint32_t off = (uint32_t)(bn * AST + kk) * 2;
            *(__half*)(smem + SMP_BHI + off) = h;
            *(__half*)(smem + SMP_BLO + off) = l;
        }
        __syncthreads();

#pragma unroll
        for (int ks = 0; ks < 4; ks++) {
            const int k0 = ks * 16;
            uint32_t ahr[8], alr[8];
#pragma unroll
            for (int t = 0; t < 2; t++) {
                int r0 = warp_r * 32 + t * 16 + gid;
                uint32_t o0 = (uint32_t)(r0 * AST + k0 + tig * 2) * 2;
                uint32_t o1 = (uint32_t)((r0 + 8) * AST + k0 + tig * 2) * 2;
                ahr[t * 4 + 0] = *(const uint32_t*)(smem + SMP_AHI + o0);
                ahr[t * 4 + 1] = *(const uint32_t*)(smem + SMP_AHI + o1);
                ahr[t * 4 + 2] = *(const uint32_t*)(smem + SMP_AHI + o0 + 16);
                ahr[t * 4 + 3] = *(const uint32_t*)(smem + SMP_AHI + o1 + 16);
                alr[t * 4 + 0] = *(const uint32_t*)(smem + SMP_ALO + o0);
                alr[t * 4 + 1] = *(const uint32_t*)(smem + SMP_ALO + o1);
                alr[t * 4 + 2] = *(const uint32_t*)(smem + SMP_ALO + o0 + 16);
                alr[t * 4 + 3] = *(const uint32_t*)(smem + SMP_ALO + o1 + 16);
            }
#pragma unroll
            for (int j = 0; j < 8; j++) {
                int n = warp_c * 64 + j * 8 + gid;
                uint32_t ob = (uint32_t)(n * AST + k0 + tig * 2) * 2;
                uint32_t bh0 = *(const uint32_t*)(smem + SMP_BHI + ob);
                uint32_t bh1 = *(const uint32_t*)(smem + SMP_BHI + ob + 16);
                uint32_t bl0 = *(const uint32_t*)(smem + SMP_BLO + ob);
                uint32_t bl1 = *(const uint32_t*)(smem + SMP_BLO + ob + 16);
#pragma unroll
                for (int t = 0; t < 2; t++) {
                    mma16816(acc[t][j], ahr + t * 4, bh0, bh1);
                    mma16816(acc[t][j], ahr + t * 4, bl0, bl1);
                    mma16816(acc[t][j], alr + t * 4, bh0, bh1);
                }
            }
        }
    }

    const float* bias_s = (const float*)(smem + SMP_BIAS);
#pragma unroll
    for (int t = 0; t < 2; t++) {
        int r_lo = row0 + warp_r * 32 + t * 16 + gid;
        int r_hi = r_lo + 8;
#pragma unroll
        for (int j = 0; j < 8; j++) {
            int col = warp_c * 64 + j * 8 + tig * 2;
            float bx = bias_s[col], by = bias_s[col + 1];
            if (r_lo < N) {
                __half2 h = __float22half2_rn(
                    make_float2(acc[t][j][0] + bx, acc[t][j][1] + by));
                *(__half2*)(Ch + (size_t)r_lo * 128 + col) = h;
            }
            if (r_hi < N) {
                __half2 h = __float22half2_rn(
                    make_float2(acc[t][j][2] + bx, acc[t][j][3] + by));
                *(__half2*)(Ch + (size_t)r_hi * 128 + col) = h;
            }
        }
    }
}

// ---------------- tensor-core SAGE GEMM (single direction, optional fused LN) --
#define SMG_BIAS  0
#define SMG_GAMMA 512
#define SMG_BETA  1024
#define SMG_STAT  1536                    // 128 rows x [warp_c][sum,sq] = 2KB
#define SMG_A     4096
#define SMG_B     (SMG_A + 128 * AST * 2)
#define SMG_TOT   (SMG_B + 128 * AST * 2)

__global__ void __launch_bounds__(256, 2) sage_mma(
        int is_user, int cur, int mbuf,
        const __half* __restrict__ Wlt, const __half* __restrict__ Wrt,
        const float* __restrict__ bias,
        const float* __restrict__ lgamma, const float* __restrict__ lbeta,
        float* __restrict__ lnout) {
    extern __shared__ char smem[];
    const int tid = threadIdx.x;
    const int wid = tid >> 5;
    const int lane = tid & 31;

    const int tile = blockIdx.x;
    const __half* __restrict__ meanh = is_user ? mu(mbuf) : mb(mbuf);
    const __half* __restrict__ Xh    = is_user ? uh(cur) : bh(cur);
    __half* __restrict__ Oh          = is_user ? uh(cur ^ 1) : bh(cur ^ 1);
    const int N = is_user ? NU : NB;
    const int row0 = tile * 128;
    const bool do_ln = (lnout != nullptr);

    if (tid < 128) {
        *(float*)(smem + SMG_BIAS + tid * 4) = bias[tid];
        if (do_ln) {
            *(float*)(smem + SMG_GAMMA + tid * 4) = lgamma[tid];
            *(float*)(smem + SMG_BETA + tid * 4)  = lbeta[tid];
        }
    }

    const int warp_r = wid >> 1;
    const int warp_c = wid & 1;
    const int gid = lane >> 2;
    const int tig = lane & 3;

    float acc[2][8][4];
#pragma unroll
    for (int t = 0; t < 2; t++)
#pragma unroll
        for (int j = 0; j < 8; j++)
#pragma unroll
            for (int q = 0; q < 4; q++) acc[t][j][q] = 0.f;

    const int a_kq = (tid & 15) * 4;
    const int a_m0 = tid >> 4;
    const int bn = tid & 127;
    const int bk0 = (tid >> 7) * 32;

#pragma unroll 1
    for (int c = 0; c < 4; c++) {
        __syncthreads();

        const int kg0 = c * 64;
        const bool xpart = (kg0 >= 128);
        const __half* __restrict__ asrc = xpart ? Xh : meanh;
        const int akoff = xpart ? kg0 - 128 : kg0;
#pragma unroll
        for (int i = 0; i < 8; i++) {
            int m = a_m0 + i * 16;
            int gr = row0 + m;
            uint2 vh = make_uint2(0u, 0u);
            if (gr < N) vh = *(const uint2*)(asrc + (size_t)gr * 128 + akoff + a_kq);
            *(uint2*)(smem + SMG_A + (uint32_t)(m * AST + a_kq) * 2) = vh;
        }

        const __half* __restrict__ wsrc = (xpart ? Wrt : Wlt) + (size_t)bn * 128
                                          + (xpart ? kg0 - 128 : kg0) + bk0;
#pragma unroll
        for (int j = 0; j < 4; j++) {
            uint4 v = *(const uint4*)(wsrc + j * 8);
            *(uint4*)(smem + SMG_B + (uint32_t)(bn * AST + bk0 + j * 8) * 2) = v;
        }
        __syncthreads();

#pragma unroll
        for (int ks = 0; ks < 4; ks++) {
            const int k0 = ks * 16;
            uint32_t ahr[8];
#pragma unroll
            for (int t = 0; t < 2; t++) {
                int r0 = warp_r * 32 + t * 16 + gid;
                uint32_t o0 = (uint32_t)(r0 * AST + k0 + tig * 2) * 2;
                uint32_t o1 = (uint32_t)((r0 + 8) * AST + k0 + tig * 2) * 2;
                ahr[t * 4 + 0] = *(const uint32_t*)(smem + SMG_A + o0);
                ahr[t * 4 + 1] = *(const uint32_t*)(smem + SMG_A + o1);
                ahr[t * 4 + 2] = *(const uint32_t*)(smem + SMG_A + o0 + 16);
                ahr[t * 4 + 3] = *(const uint32_t*)(smem + SMG_A + o1 + 16);
            }
#pragma unroll
            for (int j = 0; j < 8; j++) {
                int n = warp_c * 64 + j * 8 + gid;
                uint32_t ob = (uint32_t)(n * AST + k0 + tig * 2) * 2;
                uint32_t bh0 = *(const uint32_t*)(smem + SMG_B + ob);
                uint32_t bh1 = *(const uint32_t*)(smem + SMG_B + ob + 16);
#pragma unroll
                for (int t = 0; t < 2; t++)
                    mma16816(acc[t][j], ahr + t * 4, bh0, bh1);
            }
        }
    }

    const float* bias_s = (const float*)(smem + SMG_BIAS);

    // fold bias + relu into acc (needed by both epilogues)
#pragma unroll
    for (int t = 0; t < 2; t++)
#pragma unroll
        for (int j = 0; j < 8; j++) {
            int col = warp_c * 64 + j * 8 + tig * 2;
            float bx = bias_s[col], by = bias_s[col + 1];
            acc[t][j][0] = fmaxf(acc[t][j][0] + bx, 0.f);
            acc[t][j][1] = fmaxf(acc[t][j][1] + by, 0.f);
            acc[t][j][2] = fmaxf(acc[t][j][2] + bx, 0.f);
            acc[t][j][3] = fmaxf(acc[t][j][3] + by, 0.f);
        }

    if (!do_ln) {
        // intermediate layer: fp16 hi store
#pragma unroll
        for (int t = 0; t < 2; t++) {
            int r_lo = row0 + warp_r * 32 + t * 16 + gid;
            int r_hi = r_lo + 8;
#pragma unroll
            for (int j = 0; j < 8; j++) {
                int col = warp_c * 64 + j * 8 + tig * 2;
                if (r_lo < N) {
                    __half2 h = __float22half2_rn(make_float2(acc[t][j][0], acc[t][j][1]));
                    *(__half2*)(Oh + (size_t)r_lo * 128 + col) = h;
                }
                if (r_hi < N) {
                    __half2 h = __float22half2_rn(make_float2(acc[t][j][2], acc[t][j][3]));
                    *(__half2*)(Oh + (size_t)r_hi * 128 + col) = h;
                }
            }
        }
        return;
    }

    // ---- fused LayerNorm epilogue (fp32 stats, fp32 out) ----
    float* stat = (float*)(smem + SMG_STAT);   // [128][2 warp_c][2 {sum,sq}]
    float ps[2][2], pq[2][2];                  // [t][lohi] band partials
#pragma unroll
    for (int t = 0; t < 2; t++)
#pragma unroll
        for (int h = 0; h < 2; h++) { ps[t][h] = 0.f; pq[t][h] = 0.f; }
#pragma unroll
    for (int t = 0; t < 2; t++)
#pragma unroll
        for (int j = 0; j < 8; j++) {
            ps[t][0] += acc[t][j][0] + acc[t][j][1];
            pq[t][0] += acc[t][j][0] * acc[t][j][0] + acc[t][j][1] * acc[t][j][1];
            ps[t][1] += acc[t][j][2] + acc[t][j][3];
            pq[t][1] += acc[t][j][2] * acc[t][j][2] + acc[t][j][3] * acc[t][j][3];
        }
    // quad reduce over tig (lanes gid*4 + tig)
#pragma unroll
    for (int o = 1; o < 4; o <<= 1)
#pragma unroll
        for (int t = 0; t < 2; t++)
#pragma unroll
            for (int h = 0; h < 2; h++) {
                ps[t][h] += __shfl_xor_sync(0xffffffffu, ps[t][h], o);
                pq[t][h] += __shfl_xor_sync(0xffffffffu, pq[t][h], o);
            }
    __syncthreads();   // (reuses smem region distinct from A/B; syncs before stat writes)
    if (tig == 0) {
#pragma unroll
        for (int t = 0; t < 2; t++)
#pragma unroll
            for (int h = 0; h < 2; h++) {
                int r = warp_r * 32 + t * 16 + h * 8 + gid;   // row in tile
                stat[r * 4 + warp_c * 2 + 0] = ps[t][h];
                stat[r * 4 + warp_c * 2 + 1] = pq[t][h];
            }
    }
    __syncthreads();

    const float* gamma_s = (const float*)(smem + SMG_GAMMA);
    const float* beta_s  = (const float*)(smem + SMG_BETA);
#pragma unroll
    for (int t = 0; t < 2; t++)
#pragma unroll
        for (int h = 0; h < 2; h++) {
            int r = warp_r * 32 + t * 16 + h * 8 + gid;
            int gr = row0 + r;
            if (gr >= N) continue;
            float sum = stat[r * 4 + 0] + stat[r * 4 + 2];
            float sq  = stat[r * 4 + 1] + stat[r * 4 + 3];
            float mean = sum * (1.0f / 128.0f);
            float var  = sq * (1.0f / 128.0f) - mean * mean;
            float rs   = rsqrtf(var + 1e-5f);
            float* op = lnout + (size_t)(is_user ? gr : NU + gr) * 128;
#pragma unroll
            for (int j = 0; j < 8; j++) {
                int col = warp_c * 64 + j * 8 + tig * 2;
                float vx = acc[t][j][h * 2 + 0];
                float vy = acc[t][j][h * 2 + 1];
                float2 o;
                o.x = (vx - mean) * rs * gamma_s[col] + beta_s[col];
                o.y = (vy - mean) * rs * gamma_s[col + 1] + beta_s[col + 1];
                *(float2*)(op + col) = o;
            }
        }
}

// ---------------- launch --------------------------------------------------------
extern "C" void kernel_launch(void* const* d_in, const int* in_sizes, int n_in,
                              void* d_out, int out_size) {
    const float* user_x = (const float*)d_in[0];
    const float* book_x = (const float*)d_in[1];
    const int*   esrc   = (const int*)d_in[2];
    const int*   edst   = (const int*)d_in[3];
    const float* upw    = (const float*)d_in[4];
    const float* upb    = (const float*)d_in[5];
    const float* bpw    = (const float*)d_in[6];
    const float* bpb    = (const float*)d_in[7];
    const float* Wl     = (const float*)d_in[8];
    const float* bl_    = (const float*)d_in[9];
    const float* Wr     = (const float*)d_in[10];
    const float* ug     = (const float*)d_in[11];
    const float* ube    = (const float*)d_in[12];
    const float* bg     = (const float*)d_in[13];
    const float* bbe    = (const float*)d_in[14];
    float* out = (float*)d_out;

    (void)in_sizes; (void)n_in; (void)out_size;

    static cudaStream_t sB = 0, sU = 0;
    static cudaEvent_t evIn = 0, evProj = 0, evBuild = 0;
    static cudaEvent_t evSb[3], evSu[3];
    if (!sB) {
        cudaStreamCreateWithFlags(&sB, cudaStreamNonBlocking);
        cudaStreamCreateWithFlags(&sU, cudaStreamNonBlocking);
        cudaEventCreateWithFlags(&evIn, cudaEventDisableTiming);
        cudaEventCreateWithFlags(&evProj, cudaEventDisableTiming);
        cudaEventCreateWithFlags(&evBuild, cudaEventDisableTiming);
        for (int i = 0; i < 3; i++) {
            cudaEventCreateWithFlags(&evSb[i], cudaEventDisableTiming);
            cudaEventCreateWithFlags(&evSu[i], cudaEventDisableTiming);
        }
    }

    cudaFuncSetAttribute(proj_mma, cudaFuncAttributeMaxDynamicSharedMemorySize, SMP_TOT);
    cudaFuncSetAttribute(sage_mma, cudaFuncAttributeMaxDynamicSharedMemorySize, SMG_TOT);

    int* d_offs_u; cudaGetSymbolAddress((void**)&d_offs_u, g_offs_u);
    int* d_offs_b; cudaGetSymbolAddress((void**)&d_offs_b, g_offs_b);
    int* d_deg_u;  cudaGetSymbolAddress((void**)&d_deg_u,  g_deg_u);
    int* d_deg_b;  cudaGetSymbolAddress((void**)&d_deg_b,  g_deg_b);
    int* d_bsum_u; cudaGetSymbolAddress((void**)&d_bsum_u, g_bsum_u);
    int* d_bsum_b; cudaGetSymbolAddress((void**)&d_bsum_b, g_bsum_b);
    int* d_cur_u;  cudaGetSymbolAddress((void**)&d_cur_u,  g_cur_u);
    int* d_cur_b;  cudaGetSymbolAddress((void**)&d_cur_b,  g_cur_b);
    __half* d_wlt; cudaGetSymbolAddress((void**)&d_wlt, g_wlt);
    __half* d_wrt; cudaGetSymbolAddress((void**)&d_wrt, g_wrt);

    // ---- fork: proj chain on sB, CSR build on default stream ----
    cudaEventRecord(evIn, 0);
    cudaStreamWaitEvent(sB, evIn, 0);
    convert_w<<<(3 * 16384 + 255) / 256, 256, 0, sB>>>(Wl, Wr);
    proj_mma<<<TU + TB, 256, SMP_TOT, sB>>>(user_x, book_x, upw, upb, bpw, bpb);
    cudaEventRecord(evProj, sB);

    cudaMemsetAsync(d_deg_u, 0, NU * sizeof(int), 0);
    cudaMemsetAsync(d_deg_b, 0, NB * sizeof(int), 0);
    deg_kernel<<<(NE + 255) / 256, 256>>>(esrc, edst);
    scan_blocks<<<NBLK_U, 1024>>>(d_deg_u, d_offs_u, d_bsum_u, NU);
    scan_blocks<<<NBLK_B, 1024>>>(d_deg_b, d_offs_b, d_bsum_b, NB);
    scan_small<<<1, 256>>>(d_bsum_u, NBLK_U);
    scan_small<<<1, 256>>>(d_bsum_b, NBLK_B);
    scan_add<<<(NU + 255) / 256, 256>>>(d_offs_u, d_bsum_u, d_cur_u, NU, NBLK_U);
    scan_add<<<(NB + 255) / 256, 256>>>(d_offs_b, d_bsum_b, d_cur_b, NB, NBLK_B);
    fill_kernel<<<(NE + 255) / 256, 256>>>(esrc, edst);
    cudaEventRecord(evBuild, 0);

    cudaStreamWaitEvent(sB, evBuild, 0);
    cudaStreamWaitEvent(sU, evBuild, 0);
    cudaStreamWaitEvent(sU, evProj, 0);

    // ---- pipelined direction chains: book on sB, user on sU; layer 2 fuses LN ----
    const int GBB = (int)(((size_t)NB * 32 + 255) / 256);
    const int GBU = (int)(((size_t)NU * 32 + 255) / 256);
    int cur = 0;
    for (int l = 0; l < 3; l++) {
        const __half* wlt = d_wlt + (size_t)l * 16384;
        const __half* wrt = d_wrt + (size_t)l * 16384;
        const float* bb = bl_ + (size_t)l * 128;
        const bool last = (l == 2);

        if (l > 0) cudaStreamWaitEvent(sB, evSu[l - 1], 0);
        gather_mean<<<GBB, 256, 0, sB>>>(0, cur, l & 1);
        sage_mma<<<TB, 256, SMG_TOT, sB>>>(0, cur, l & 1, wlt, wrt, bb,
                                           last ? bg : (const float*)nullptr,
                                           last ? bbe : (const float*)nullptr,
                                           last ? out : (float*)nullptr);
        cudaEventRecord(evSb[l], sB);

        if (l > 0) cudaStreamWaitEvent(sU, evSb[l - 1], 0);
        gather_mean<<<GBU, 256, 0, sU>>>(1, cur, l & 1);
        sage_mma<<<TU, 256, SMG_TOT, sU>>>(1, cur, l & 1, wlt, wrt, bb,
                                           last ? ug : (const float*)nullptr,
                                           last ? ube : (const float*)nullptr,
                                           last ? out : (float*)nullptr);
        cudaEventRecord(evSu[l], sU);

        cur ^= 1;
    }

    // ---- join on default stream (graph leaf dependencies) ----
    cudaStreamWaitEvent(0, evSb[2], 0);
    cudaStreamWaitEvent(0, evSu[2], 0);
}